// round 16
// baseline (speedup 1.0000x reference)
#include <cuda_runtime.h>
#include <cuda_fp16.h>
#include <math.h>

#define NB 64
#define TT 512
#define DD 1024
#define HH 1024
#define FH 4096   // 4*H
#define MM 32768  // NB*TT

typedef unsigned long long ull;

// Scratch (device globals — no runtime allocation allowed)
__device__ __half g_xz[(size_t)TT * NB * FH];       // (t, n, 4H) fp16 : 256 MB
__device__ __half g_whf[(size_t)1024 * FH];         // Wh fp16 (cols permuted)
__device__ __half g_wxf[(size_t)1024 * FH];         // Wx fp16
__device__ __half g_xf[(size_t)MM * DD];            // x fp16
__device__ __half g_hf[2][NB * HH];                 // h fp16, double-buffered
// Barrier v2: per-block arrival slots + broadcast phase (monotonic counters)
__device__ unsigned g_arrive[128];
__device__ unsigned g_phase;

// ---- helpers ----------------------------------------------------------------
__device__ __forceinline__ unsigned s2u(const void* p) {
    return (unsigned)__cvta_generic_to_shared(p);
}
__device__ __forceinline__ void cp16(void* s, const void* g) {
    asm volatile("cp.async.cg.shared.global [%0], [%1], 16;" :: "r"(s2u(s)), "l"(g));
}
__device__ __forceinline__ unsigned ld_acquire(const unsigned* p) {
    unsigned v;
    asm volatile("ld.acquire.gpu.u32 %0, [%1];" : "=r"(v) : "l"(p) : "memory");
    return v;
}
__device__ __forceinline__ void st_release(unsigned* p, unsigned v) {
    asm volatile("st.release.gpu.u32 [%0], %1;" :: "l"(p), "r"(v) : "memory");
}
__device__ __forceinline__ void spin_until(const unsigned* p, unsigned target) {
    while (ld_acquire(p) < target) {}
}
// Fast gates (MUFU paths, flag-independent)
__device__ __forceinline__ float fsig(float x) {
    return __fdividef(1.0f, 1.0f + __expf(-x));
}
__device__ __forceinline__ float ftanh(float x) {
    return __fmaf_rn(2.0f, __fdividef(1.0f, 1.0f + __expf(-2.0f * x)), -1.0f);
}
#define LDSM_X4(r0, r1, r2, r3, addr) \
    asm volatile("ldmatrix.sync.aligned.m8n8.x4.shared.b16 {%0,%1,%2,%3}, [%4];" \
                 : "=r"(r0), "=r"(r1), "=r"(r2), "=r"(r3) : "r"(addr))
#define LDSM_X4T(r0, r1, r2, r3, addr) \
    asm volatile("ldmatrix.sync.aligned.m8n8.x4.trans.shared.b16 {%0,%1,%2,%3}, [%4];" \
                 : "=r"(r0), "=r"(r1), "=r"(r2), "=r"(r3) : "r"(addr))
#define MMA16816F16(d0, d1, d2, d3, a0, a1, a2, a3, b0, b1) \
    asm volatile("mma.sync.aligned.m16n8k16.row.col.f32.f16.f16.f32 " \
                 "{%0,%1,%2,%3}, {%4,%5,%6,%7}, {%8,%9}, {%0,%1,%2,%3};" \
                 : "+f"(d0), "+f"(d1), "+f"(d2), "+f"(d3) \
                 : "r"(a0), "r"(a1), "r"(a2), "r"(a3), "r"(b0), "r"(b1))

// ---------------------------------------------------------------------------
// Init / precompute kernels
// ---------------------------------------------------------------------------
__global__ void init_kernel(const float* __restrict__ h0) {
    int i = blockIdx.x * blockDim.x + threadIdx.x;
    if (i < 128) g_arrive[i] = 0;
    if (i == 128) g_phase = 0;
    if (i < NB * HH) {
        g_hf[0][i] = __float2half_rn(h0[i]);
    }
}

// Wh fp16 + block-column permute: col_new = blk*32 + g*8 + j
__global__ void split_wh_kernel(const float* __restrict__ Wh) {
    int i = blockIdx.x * blockDim.x + threadIdx.x;
    if (i >= DD * FH) return;
    int k = i >> 12;
    int co = i & 4095;
    int g = co >> 10;
    int within = co & 1023;
    int blk = within >> 3;
    int j = within & 7;
    size_t col = (size_t)blk * 32 + g * 8 + j;
    g_whf[(size_t)k * FH + col] = __float2half_rn(Wh[i]);
}

// Wx fp16 (single product)
__global__ void split_wx_kernel(const float* __restrict__ Wx) {
    int i = blockIdx.x * blockDim.x + threadIdx.x;
    if (i >= DD * FH) return;
    g_wxf[i] = __float2half_rn(Wx[i]);
}

// Vectorized x -> fp16 (float4 in, 2x half2 out)
__global__ void split_x_kernel(const float* __restrict__ X) {
    size_t i = ((size_t)blockIdx.x * blockDim.x + threadIdx.x) * 4;
    if (i >= (size_t)MM * DD) return;
    float4 v = *(const float4*)(X + i);
    *(__half2*)(g_xf + i)     = __floats2half2_rn(v.x, v.y);
    *(__half2*)(g_xf + i + 2) = __floats2half2_rn(v.z, v.w);
}

// ---------------------------------------------------------------------------
// GEMM1 (fp16 single product): xz = x @ Wx + b, K=1024, fp16 output.
// 128x128x32 tiles, 256 threads, 3-stage cp.async.
// ---------------------------------------------------------------------------
#define G1_ASTR 40
#define G1_BSTR 136
#define G1_ABYTES (128 * G1_ASTR * 2)
#define G1_BBYTES (32 * G1_BSTR * 2)
#define G1_STAGE  (G1_ABYTES + G1_BBYTES)
#define G1_SMEM   (3 * G1_STAGE)
#define G1_NSLAB  32

__global__ __launch_bounds__(256) void gemm1_mma(const float* __restrict__ b) {
    extern __shared__ __align__(16) char sm1[];

    const int tid = threadIdx.x;
    const int lane = tid & 31;
    const int wid = tid >> 5;
    const int warp_m = wid >> 1;
    const int warp_n = wid & 1;
    const int m0 = blockIdx.y * 128;
    const int n0 = blockIdx.x * 128;

    const int lr = lane & 7;
    const int lg = lane >> 3;
    const int a_row_off = ((lg & 1) << 3) + lr;
    const int a_k_off = (lg >> 1) << 3;
    const int bt_row = lr + ((lg & 1) << 3);
    const int bt_c8 = (lane >> 4) << 3;

    float d[2][8][4];
#pragma unroll
    for (int mt = 0; mt < 2; mt++)
#pragma unroll
        for (int nt = 0; nt < 8; nt++)
#pragma unroll
            for (int r = 0; r < 4; r++) d[mt][nt][r] = 0.0f;

    auto prefetch = [&](int sp) {
        char* stg = sm1 + (sp % 3) * G1_STAGE;
        __half* As = (__half*)stg;
        __half* Bs = (__half*)(stg + G1_ABYTES);
        const int kin = sp * 32;
#pragma unroll
        for (int i = 0; i < 2; i++) {
            int idx = tid + i * 256;
            int row = idx >> 2, ch = idx & 3;
            cp16(&As[row * G1_ASTR + ch * 8],
                 &g_xf[(size_t)(m0 + row) * DD + kin + ch * 8]);
        }
#pragma unroll
        for (int i = 0; i < 2; i++) {
            int idx = tid + i * 256;
            int row = idx >> 4, ch = idx & 15;
            cp16(&Bs[row * G1_BSTR + ch * 8],
                 &g_wxf[(size_t)(kin + row) * FH + n0 + ch * 8]);
        }
        asm volatile("cp.async.commit_group;");
    };

    prefetch(0);
    prefetch(1);

    for (int s = 0; s < G1_NSLAB; s++) {
        asm volatile("cp.async.wait_group 1;");
        __syncthreads();
        if (s + 2 < G1_NSLAB) prefetch(s + 2);
        else asm volatile("cp.async.commit_group;");

        char* stg = sm1 + (s % 3) * G1_STAGE;
        const __half* As = (const __half*)stg;
        const __half* Bs = (const __half*)(stg + G1_ABYTES);

#pragma unroll
        for (int ks = 0; ks < 2; ks++) {
            const int kk0 = ks * 16;
            unsigned a[2][4];
#pragma unroll
            for (int mt = 0; mt < 2; mt++) {
                unsigned addr = s2u(&As[(warp_m * 32 + mt * 16 + a_row_off) * G1_ASTR
                                        + kk0 + a_k_off]);
                LDSM_X4(a[mt][0], a[mt][1], a[mt][2], a[mt][3], addr);
            }
            unsigned bf[4][4];
#pragma unroll
            for (int np = 0; np < 4; np++) {
                unsigned addr = s2u(&Bs[(kk0 + bt_row) * G1_BSTR
                                        + warp_n * 64 + np * 16 + bt_c8]);
                LDSM_X4T(bf[np][0], bf[np][1], bf[np][2], bf[np][3], addr);
            }
#pragma unroll
            for (int mt = 0; mt < 2; mt++)
#pragma unroll
                for (int nt = 0; nt < 8; nt++) {
                    unsigned b0 = bf[nt >> 1][(nt & 1) * 2 + 0];
                    unsigned b1 = bf[nt >> 1][(nt & 1) * 2 + 1];
                    MMA16816F16(d[mt][nt][0], d[mt][nt][1], d[mt][nt][2], d[mt][nt][3],
                                a[mt][0], a[mt][1], a[mt][2], a[mt][3], b0, b1);
                }
        }
    }

    const int r4 = lane >> 2;
    const int c2 = (lane & 3) * 2;
#pragma unroll
    for (int mt = 0; mt < 2; mt++) {
        int mbase = m0 + warp_m * 32 + mt * 16;
#pragma unroll
        for (int nt = 0; nt < 8; nt++) {
            int col = n0 + warp_n * 64 + nt * 8 + c2;
            float b0 = b[col], b1 = b[col + 1];
            int m = mbase + r4;
            int nb = m >> 9, tl = m & 511;
            *(__half2*)&g_xz[(size_t)(tl * NB + nb) * FH + col] =
                __floats2half2_rn(d[mt][nt][0] + b0, d[mt][nt][1] + b1);
            m += 8; nb = m >> 9; tl = m & 511;
            *(__half2*)&g_xz[(size_t)(tl * NB + nb) * FH + col] =
                __floats2half2_rn(d[mt][nt][2] + b0, d[mt][nt][3] + b1);
        }
    }
}

// ---------------------------------------------------------------------------
// Persistent recurrence kernel — fp16 single-product, 2k x 4m x 2c warps.
// 128 blocks x 512 threads. W (fp16, 80 KB) resident in SMEM; h (fp16,
// 128 KB) staged per step in 4 slabs, ALL issued at step start. z = h * W.
// out[] store deferred past barrier arrival; no threadfence (st.release).
// ---------------------------------------------------------------------------
#define WS_STR 40    // fp16; 80 B rows
#define HS_STR 264   // fp16; 528 B rows (odd multiple of 16B)
#define KSLAB 256
#define HS_STAGE_B (64 * HS_STR * 2)                 // 33792
#define SMEM_WS_B (1024 * WS_STR * 2)                // 81920
#define P_SMEM (SMEM_WS_B + 4 * HS_STAGE_B)          // 217088

__global__ __launch_bounds__(512, 1) void lstm_persistent(float* __restrict__ out) {
    extern __shared__ __align__(16) char smp[];
    __half* ws = (__half*)smp;                        // [1024][WS_STR]
    __half* hsm = (__half*)(smp + SMEM_WS_B);         // 4 stages
    float* zbuf = (float*)(smp + SMEM_WS_B);          // alias of stages 0-1: [2][64][33]

    const int tid = threadIdx.x;
    const int lane = tid & 31;
    const int wid = tid >> 5;
    const int warp_k = wid >> 3;        // 0..1 (k-half)
    const int warp_m = (wid >> 1) & 3;  // 0..3 (16 rows each)
    const int warp_c = wid & 1;         // 0..1 (16 cols each)
    const int blk = blockIdx.x;

    // --- Load this block's W slice into SMEM (once) ---
    {
        const __half* wsrc = g_whf + (size_t)blk * 32;
#pragma unroll
        for (int i = 0; i < 8; i++) {
            int c = tid + i * 512;          // 0..4095 16B-chunks
            int row = c >> 2, q = c & 3;
            *(uint4*)&ws[row * WS_STR + q * 8] =
                *(const uint4*)&wsrc[(size_t)row * FH + q * 8];
        }
    }
    __syncthreads();

    // ldmatrix lane addressing
    const int lr = lane & 7;
    const int lg = lane >> 3;
    const int a_row_off = ((lg & 1) << 3) + lr;   // row within 16
    const int a_k_off = (lg >> 1) << 3;           // 0 or 8
    const int bt_row = lr + ((lg & 1) << 3);      // k row within 16
    const int bt_c8 = (lane >> 4) << 3;           // 0 or 8 (col half)

    // epilogue mapping: 1 output per thread
    const int e_n = tid >> 3;
    const int e_j = tid & 7;
    const int J0 = blk * 8;
    float creg = 0.0f;

    for (int t = 0; t < TT; t++) {
        const int par = t & 1;
        const __half* __restrict__ hf = g_hf[par];

        float d[2][4];
#pragma unroll
        for (int ct = 0; ct < 2; ct++)
#pragma unroll
            for (int r = 0; r < 4; r++) d[ct][r] = 0.0f;

        // Issue ALL 4 slab loads up front (one commit group each)
#pragma unroll
        for (int s = 0; s < 4; s++) {
            const int hk = s * KSLAB;
            __half* dst = hsm + s * 64 * HS_STR;
#pragma unroll
            for (int i = 0; i < 4; i++) {
                int idx = tid + i * 512;    // 2048 chunks of 16B
                int n = idx >> 5, ch = idx & 31;
                cp16(&dst[n * HS_STR + ch * 8], &hf[n * HH + hk + ch * 8]);
            }
            asm volatile("cp.async.commit_group;");
        }

        // xz prefetch (fp16; after cp.async issue so the slab path leads)
        const __half* xr = g_xz + (size_t)(t * NB + e_n) * FH + J0 + e_j;
        float x0 = __half2float(__ldg(xr));
        float x1 = __half2float(__ldg(xr + 1024));
        float x2 = __half2float(__ldg(xr + 2048));
        float x3 = __half2float(__ldg(xr + 3072));

        // Compute slab s after its group lands (wait_group 3-s pending)
#define REC_SLAB(s, wcnt)                                                          \
        {                                                                          \
            asm volatile("cp.async.wait_group %0;" :: "n"(wcnt));                  \
            __syncthreads();                                                       \
            const __half* hbuf = hsm + (s) * 64 * HS_STR;                          \
            const int kw = (s) * KSLAB;                                            \
            _Pragma("unroll")                                                      \
            for (int ks = 0; ks < 8; ks++) {                                       \
                const int kk0 = warp_k * 128 + ks * 16;                            \
                unsigned a0, a1, a2, a3;                                           \
                unsigned aaddr = s2u(&hbuf[(warp_m * 16 + a_row_off) * HS_STR      \
                                           + kk0 + a_k_off]);                      \
                LDSM_X4(a0, a1, a2, a3, aaddr);                                    \
                unsigned bf0, bf1, bf2, bf3;                                       \
                unsigned baddr = s2u(&ws[(kw + kk0 + bt_row) * WS_STR              \
                                         + warp_c * 16 + bt_c8]);                  \
                LDSM_X4T(bf0, bf1, bf2, bf3, baddr);                               \
                MMA16816F16(d[0][0], d[0][1], d[0][2], d[0][3],                    \
                            a0, a1, a2, a3, bf0, bf1);                             \
                MMA16816F16(d[1][0], d[1][1], d[1][2], d[1][3],                    \
                            a0, a1, a2, a3, bf2, bf3);                             \
            }                                                                      \
        }

        REC_SLAB(0, 3)
        REC_SLAB(1, 2)
        REC_SLAB(2, 1)
        REC_SLAB(3, 0)
#undef REC_SLAB

        __syncthreads();   // all compute done; zbuf (alias of stages 0-1) now safe

        // Scatter partials: zbuf[warp_k][n][c]; warp tile = 16 rows x 16 cols
        {
            const int r4 = lane >> 2;
            const int c2 = (lane & 3) * 2;
            const int nb = warp_m * 16 + r4;
#pragma unroll
            for (int ct = 0; ct < 2; ct++) {
                const int c = warp_c * 16 + ct * 8 + c2;
                zbuf[(warp_k * 64 + nb) * 33 + c] = d[ct][0];
                zbuf[(warp_k * 64 + nb) * 33 + c + 1] = d[ct][1];
                zbuf[(warp_k * 64 + nb + 8) * 33 + c] = d[ct][2];
                zbuf[(warp_k * 64 + nb + 8) * 33 + c + 1] = d[ct][3];
            }
        }
        __syncthreads();

        // Gate epilogue: 1 fixed (n, j) output per thread; c in register
        float hn;
        {
            const int n = e_n, col = J0 + e_j;
            float zi = zbuf[n * 33 + e_j +  0] + zbuf[(64 + n) * 33 + e_j +  0] + x0;
            float zf = zbuf[n * 33 + e_j +  8] + zbuf[(64 + n) * 33 + e_j +  8] + x1;
            float zo = zbuf[n * 33 + e_j + 16] + zbuf[(64 + n) * 33 + e_j + 16] + x2;
            float zg = zbuf[n * 33 + e_j + 24] + zbuf[(64 + n) * 33 + e_j + 24] + x3;

            float iv = fsig(zi);
            float fv = fsig(zf);
            float ov = fsig(zo);
            float gv = ftanh(zg);

            float cn = fv * creg + iv * gv;
            creg = cn;
            hn = ov * ftanh(cn);

            g_hf[par ^ 1][n * HH + col] = __float2half_rn(hn);
        }

        // Grid-wide barrier; out[] store deferred past arrival (overlaps spin)
        if (t + 1 < TT) {
            const unsigned target = (unsigned)(t + 1);
            __syncthreads();                    // all h writes done (CTA scope)
            if (tid == 0) st_release(&g_arrive[blk], target);  // release orders them
            out[((size_t)e_n * TT + t) * HH + J0 + e_j] = hn;
            if (blk == 0) {
                if (tid < 128) spin_until(&g_arrive[tid], target);
                __syncthreads();
                if (tid == 0) st_release(&g_phase, target);
            }
            if (tid == 0) spin_until(&g_phase, target);
            __syncthreads();
        } else {
            out[((size_t)e_n * TT + t) * HH + J0 + e_j] = hn;
        }
    }
}

// ---------------------------------------------------------------------------
// Launcher (graph-capturable: kernel launches only)
// ---------------------------------------------------------------------------
extern "C" void kernel_launch(void* const* d_in, const int* in_sizes, int n_in,
                              void* d_out, int out_size) {
    const float* x  = (const float*)d_in[0];
    const float* h0 = (const float*)d_in[1];
    const float* Wx = (const float*)d_in[2];
    const float* Wh = (const float*)d_in[3];
    const float* b  = (const float*)d_in[4];
    float* out = (float*)d_out;

    static int attr_set = 0;
    if (!attr_set) {
        cudaFuncSetAttribute(lstm_persistent,
                             cudaFuncAttributeMaxDynamicSharedMemorySize, P_SMEM);
        cudaFuncSetAttribute(gemm1_mma,
                             cudaFuncAttributeMaxDynamicSharedMemorySize, G1_SMEM);
        attr_set = 1;
    }

    init_kernel<<<(NB * HH + 255) / 256, 256>>>(h0);
    split_wh_kernel<<<(DD * FH + 255) / 256, 256>>>(Wh);
    split_wx_kernel<<<(DD * FH + 255) / 256, 256>>>(Wx);
    split_x_kernel<<<((size_t)MM * DD / 4 + 255) / 256, 256>>>(x);

    dim3 g1(FH / 128, MM / 128);   // (32, 256)
    gemm1_mma<<<g1, 256, G1_SMEM>>>(b);

    lstm_persistent<<<128, 512, P_SMEM>>>(out);
}

// round 17
// speedup vs baseline: 1.0045x; 1.0045x over previous
#include <cuda_runtime.h>
#include <cuda_fp16.h>
#include <math.h>

#define NB 64
#define TT 512
#define DD 1024
#define HH 1024
#define FH 4096   // 4*H
#define MM 32768  // NB*TT

typedef unsigned long long ull;

// Scratch (device globals — no runtime allocation allowed)
__device__ __half g_xz[(size_t)TT * NB * FH];       // (t, n, 4H) fp16 : 256 MB
__device__ __half g_whf[(size_t)1024 * FH];         // Wh fp16 (cols permuted)
__device__ __half g_wxf[(size_t)1024 * FH];         // Wx fp16
__device__ __half g_xf[(size_t)MM * DD];            // x fp16
__device__ __half g_hf[2][NB * HH];                 // h fp16, double-buffered
// Barrier v2: per-block arrival slots + broadcast phase (monotonic counters)
__device__ unsigned g_arrive[128];
__device__ unsigned g_phase;

// ---- helpers ----------------------------------------------------------------
__device__ __forceinline__ unsigned s2u(const void* p) {
    return (unsigned)__cvta_generic_to_shared(p);
}
__device__ __forceinline__ void cp16(void* s, const void* g) {
    asm volatile("cp.async.cg.shared.global [%0], [%1], 16;" :: "r"(s2u(s)), "l"(g));
}
__device__ __forceinline__ unsigned ld_acquire(const unsigned* p) {
    unsigned v;
    asm volatile("ld.acquire.gpu.u32 %0, [%1];" : "=r"(v) : "l"(p) : "memory");
    return v;
}
__device__ __forceinline__ void st_release(unsigned* p, unsigned v) {
    asm volatile("st.release.gpu.u32 [%0], %1;" :: "l"(p), "r"(v) : "memory");
}
__device__ __forceinline__ void spin_until(const unsigned* p, unsigned target) {
    while (ld_acquire(p) < target) {}
}
// Fast gates (MUFU paths, flag-independent)
__device__ __forceinline__ float fsig(float x) {
    return __fdividef(1.0f, 1.0f + __expf(-x));
}
__device__ __forceinline__ float ftanh(float x) {
    return __fmaf_rn(2.0f, __fdividef(1.0f, 1.0f + __expf(-2.0f * x)), -1.0f);
}
#define LDSM_X4(r0, r1, r2, r3, addr) \
    asm volatile("ldmatrix.sync.aligned.m8n8.x4.shared.b16 {%0,%1,%2,%3}, [%4];" \
                 : "=r"(r0), "=r"(r1), "=r"(r2), "=r"(r3) : "r"(addr))
#define LDSM_X4T(r0, r1, r2, r3, addr) \
    asm volatile("ldmatrix.sync.aligned.m8n8.x4.trans.shared.b16 {%0,%1,%2,%3}, [%4];" \
                 : "=r"(r0), "=r"(r1), "=r"(r2), "=r"(r3) : "r"(addr))
#define MMA16816F16(d0, d1, d2, d3, a0, a1, a2, a3, b0, b1) \
    asm volatile("mma.sync.aligned.m16n8k16.row.col.f32.f16.f16.f32 " \
                 "{%0,%1,%2,%3}, {%4,%5,%6,%7}, {%8,%9}, {%0,%1,%2,%3};" \
                 : "+f"(d0), "+f"(d1), "+f"(d2), "+f"(d3) \
                 : "r"(a0), "r"(a1), "r"(a2), "r"(a3), "r"(b0), "r"(b1))
#define BAR_SYNC(id, cnt) \
    asm volatile("bar.sync %0, %1;" :: "r"(id), "r"(cnt) : "memory")

// ---------------------------------------------------------------------------
// Init / precompute kernels
// ---------------------------------------------------------------------------
__global__ void init_kernel(const float* __restrict__ h0) {
    int i = blockIdx.x * blockDim.x + threadIdx.x;
    if (i < 128) g_arrive[i] = 0;
    if (i == 128) g_phase = 0;
    if (i < NB * HH) {
        g_hf[0][i] = __float2half_rn(h0[i]);
    }
}

// Wh fp16 + block-column permute, vectorized: one thread handles an 8-col
// unit (k, g, blk): src cols g*1024+blk*8..+8 -> dst cols blk*32+g*8..+8.
__global__ void split_wh_kernel(const float* __restrict__ Wh) {
    int i = blockIdx.x * blockDim.x + threadIdx.x;
    if (i >= DD * FH / 8) return;
    int k = i >> 9;
    int u = i & 511;
    int g = u >> 7;
    int blk = u & 127;
    const float* src = Wh + (size_t)k * FH + g * 1024 + blk * 8;
    float4 v0 = *(const float4*)src;
    float4 v1 = *(const float4*)(src + 4);
    __half2 h0 = __floats2half2_rn(v0.x, v0.y);
    __half2 h1 = __floats2half2_rn(v0.z, v0.w);
    __half2 h2 = __floats2half2_rn(v1.x, v1.y);
    __half2 h3 = __floats2half2_rn(v1.z, v1.w);
    uint4 o;
    o.x = *(unsigned*)&h0; o.y = *(unsigned*)&h1;
    o.z = *(unsigned*)&h2; o.w = *(unsigned*)&h3;
    *(uint4*)&g_whf[(size_t)k * FH + blk * 32 + g * 8] = o;
}

// Wx fp16, vectorized by 8
__global__ void split_wx_kernel(const float* __restrict__ Wx) {
    size_t i = ((size_t)blockIdx.x * blockDim.x + threadIdx.x) * 8;
    if (i >= (size_t)DD * FH) return;
    float4 v0 = *(const float4*)(Wx + i);
    float4 v1 = *(const float4*)(Wx + i + 4);
    __half2 h0 = __floats2half2_rn(v0.x, v0.y);
    __half2 h1 = __floats2half2_rn(v0.z, v0.w);
    __half2 h2 = __floats2half2_rn(v1.x, v1.y);
    __half2 h3 = __floats2half2_rn(v1.z, v1.w);
    uint4 o;
    o.x = *(unsigned*)&h0; o.y = *(unsigned*)&h1;
    o.z = *(unsigned*)&h2; o.w = *(unsigned*)&h3;
    *(uint4*)&g_wxf[i] = o;
}

// Vectorized x -> fp16 (float4 in, 2x half2 out)
__global__ void split_x_kernel(const float* __restrict__ X) {
    size_t i = ((size_t)blockIdx.x * blockDim.x + threadIdx.x) * 4;
    if (i >= (size_t)MM * DD) return;
    float4 v = *(const float4*)(X + i);
    *(__half2*)(g_xf + i)     = __floats2half2_rn(v.x, v.y);
    *(__half2*)(g_xf + i + 2) = __floats2half2_rn(v.z, v.w);
}

// ---------------------------------------------------------------------------
// GEMM1 (fp16 single product): xz = x @ Wx + b, K=1024, fp16 output.
// 128x128x32 tiles, 256 threads, 3-stage cp.async.
// ---------------------------------------------------------------------------
#define G1_ASTR 40
#define G1_BSTR 136
#define G1_ABYTES (128 * G1_ASTR * 2)
#define G1_BBYTES (32 * G1_BSTR * 2)
#define G1_STAGE  (G1_ABYTES + G1_BBYTES)
#define G1_SMEM   (3 * G1_STAGE)
#define G1_NSLAB  32

__global__ __launch_bounds__(256) void gemm1_mma(const float* __restrict__ b) {
    extern __shared__ __align__(16) char sm1[];

    const int tid = threadIdx.x;
    const int lane = tid & 31;
    const int wid = tid >> 5;
    const int warp_m = wid >> 1;
    const int warp_n = wid & 1;
    const int m0 = blockIdx.y * 128;
    const int n0 = blockIdx.x * 128;

    const int lr = lane & 7;
    const int lg = lane >> 3;
    const int a_row_off = ((lg & 1) << 3) + lr;
    const int a_k_off = (lg >> 1) << 3;
    const int bt_row = lr + ((lg & 1) << 3);
    const int bt_c8 = (lane >> 4) << 3;

    float d[2][8][4];
#pragma unroll
    for (int mt = 0; mt < 2; mt++)
#pragma unroll
        for (int nt = 0; nt < 8; nt++)
#pragma unroll
            for (int r = 0; r < 4; r++) d[mt][nt][r] = 0.0f;

    auto prefetch = [&](int sp) {
        char* stg = sm1 + (sp % 3) * G1_STAGE;
        __half* As = (__half*)stg;
        __half* Bs = (__half*)(stg + G1_ABYTES);
        const int kin = sp * 32;
#pragma unroll
        for (int i = 0; i < 2; i++) {
            int idx = tid + i * 256;
            int row = idx >> 2, ch = idx & 3;
            cp16(&As[row * G1_ASTR + ch * 8],
                 &g_xf[(size_t)(m0 + row) * DD + kin + ch * 8]);
        }
#pragma unroll
        for (int i = 0; i < 2; i++) {
            int idx = tid + i * 256;
            int row = idx >> 4, ch = idx & 15;
            cp16(&Bs[row * G1_BSTR + ch * 8],
                 &g_wxf[(size_t)(kin + row) * FH + n0 + ch * 8]);
        }
        asm volatile("cp.async.commit_group;");
    };

    prefetch(0);
    prefetch(1);

    for (int s = 0; s < G1_NSLAB; s++) {
        asm volatile("cp.async.wait_group 1;");
        __syncthreads();
        if (s + 2 < G1_NSLAB) prefetch(s + 2);
        else asm volatile("cp.async.commit_group;");

        char* stg = sm1 + (s % 3) * G1_STAGE;
        const __half* As = (const __half*)stg;
        const __half* Bs = (const __half*)(stg + G1_ABYTES);

#pragma unroll
        for (int ks = 0; ks < 2; ks++) {
            const int kk0 = ks * 16;
            unsigned a[2][4];
#pragma unroll
            for (int mt = 0; mt < 2; mt++) {
                unsigned addr = s2u(&As[(warp_m * 32 + mt * 16 + a_row_off) * G1_ASTR
                                        + kk0 + a_k_off]);
                LDSM_X4(a[mt][0], a[mt][1], a[mt][2], a[mt][3], addr);
            }
            unsigned bf[4][4];
#pragma unroll
            for (int np = 0; np < 4; np++) {
                unsigned addr = s2u(&Bs[(kk0 + bt_row) * G1_BSTR
                                        + warp_n * 64 + np * 16 + bt_c8]);
                LDSM_X4T(bf[np][0], bf[np][1], bf[np][2], bf[np][3], addr);
            }
#pragma unroll
            for (int mt = 0; mt < 2; mt++)
#pragma unroll
                for (int nt = 0; nt < 8; nt++) {
                    unsigned b0 = bf[nt >> 1][(nt & 1) * 2 + 0];
                    unsigned b1 = bf[nt >> 1][(nt & 1) * 2 + 1];
                    MMA16816F16(d[mt][nt][0], d[mt][nt][1], d[mt][nt][2], d[mt][nt][3],
                                a[mt][0], a[mt][1], a[mt][2], a[mt][3], b0, b1);
                }
        }
    }

    const int r4 = lane >> 2;
    const int c2 = (lane & 3) * 2;
#pragma unroll
    for (int mt = 0; mt < 2; mt++) {
        int mbase = m0 + warp_m * 32 + mt * 16;
#pragma unroll
        for (int nt = 0; nt < 8; nt++) {
            int col = n0 + warp_n * 64 + nt * 8 + c2;
            float b0 = b[col], b1 = b[col + 1];
            int m = mbase + r4;
            int nb = m >> 9, tl = m & 511;
            *(__half2*)&g_xz[(size_t)(tl * NB + nb) * FH + col] =
                __floats2half2_rn(d[mt][nt][0] + b0, d[mt][nt][1] + b1);
            m += 8; nb = m >> 9; tl = m & 511;
            *(__half2*)&g_xz[(size_t)(tl * NB + nb) * FH + col] =
                __floats2half2_rn(d[mt][nt][2] + b0, d[mt][nt][3] + b1);
        }
    }
}

// ---------------------------------------------------------------------------
// Persistent recurrence kernel — fp16 single-product, 2k x 4m x 2c warps,
// WARP-PAIR SELF-STAGING: each (k,m) pair cp.asyncs exactly the A-region it
// consumes; per-slab sync is a 64-thread named barrier (no block-wide syncs
// inside the slab loop). W resident in SMEM; 4 h-slabs issued at step start.
// ---------------------------------------------------------------------------
#define WS_STR 40    // fp16; 80 B rows
#define HS_STR 264   // fp16; 528 B rows (odd multiple of 16B)
#define KSLAB 256
#define HS_STAGE_B (64 * HS_STR * 2)                 // 33792
#define SMEM_WS_B (1024 * WS_STR * 2)                // 81920
#define P_SMEM (SMEM_WS_B + 4 * HS_STAGE_B)          // 217088

__global__ __launch_bounds__(512, 1) void lstm_persistent(float* __restrict__ out) {
    extern __shared__ __align__(16) char smp[];
    __half* ws = (__half*)smp;                        // [1024][WS_STR]
    __half* hsm = (__half*)(smp + SMEM_WS_B);         // 4 stages
    float* zbuf = (float*)(smp + SMEM_WS_B);          // alias of stages 0-1: [2][64][33]

    const int tid = threadIdx.x;
    const int lane = tid & 31;
    const int wid = tid >> 5;
    const int warp_k = wid >> 3;        // 0..1 (k-half)
    const int warp_m = (wid >> 1) & 3;  // 0..3 (16 rows each)
    const int warp_c = wid & 1;         // 0..1 (16 cols each)
    const int blk = blockIdx.x;
    const int pair_bar = 1 + warp_k * 4 + warp_m;   // named barrier id 1..8
    const int lt = warp_c * 32 + lane;              // 0..63 within pair

    // --- Load this block's W slice into SMEM (once) ---
    {
        const __half* wsrc = g_whf + (size_t)blk * 32;
#pragma unroll
        for (int i = 0; i < 8; i++) {
            int c = tid + i * 512;          // 0..4095 16B-chunks
            int row = c >> 2, q = c & 3;
            *(uint4*)&ws[row * WS_STR + q * 8] =
                *(const uint4*)&wsrc[(size_t)row * FH + q * 8];
        }
    }
    __syncthreads();

    // ldmatrix lane addressing
    const int lr = lane & 7;
    const int lg = lane >> 3;
    const int a_row_off = ((lg & 1) << 3) + lr;   // row within 16
    const int a_k_off = (lg >> 1) << 3;           // 0 or 8
    const int bt_row = lr + ((lg & 1) << 3);      // k row within 16
    const int bt_c8 = (lane >> 4) << 3;           // 0 or 8 (col half)

    // pair staging addressing: thread lt loads row m*16+(lt>>2),
    // chunks q = i*4 + (lt&3)  (lanes 0-3 -> 64B contiguous runs)
    const int st_row = warp_m * 16 + (lt >> 2);
    const int st_q4 = lt & 3;

    // epilogue mapping: 1 output per thread
    const int e_n = tid >> 3;
    const int e_j = tid & 7;
    const int J0 = blk * 8;
    float creg = 0.0f;

    for (int t = 0; t < TT; t++) {
        const int par = t & 1;
        const __half* __restrict__ hf = g_hf[par];

        // xz prefetch FIRST (its LDGs lead the LSU queue; consumed at epilogue)
        const __half* xr = g_xz + (size_t)(t * NB + e_n) * FH + J0 + e_j;
        float x0 = __half2float(__ldg(xr));
        float x1 = __half2float(__ldg(xr + 1024));
        float x2 = __half2float(__ldg(xr + 2048));
        float x3 = __half2float(__ldg(xr + 3072));

        float d[2][4];
#pragma unroll
        for (int ct = 0; ct < 2; ct++)
#pragma unroll
            for (int r = 0; r < 4; r++) d[ct][r] = 0.0f;

        // Issue this pair's 4 slab loads up front (one commit group per slab)
#pragma unroll
        for (int s = 0; s < 4; s++) {
            const int base_k = s * KSLAB + warp_k * 128;
            __half* dst = hsm + s * 64 * HS_STR;
#pragma unroll
            for (int i = 0; i < 4; i++) {
                int q = i * 4 + st_q4;      // 0..15 (16B chunks of 128 k)
                cp16(&dst[st_row * HS_STR + warp_k * 128 + q * 8],
                     &hf[st_row * HH + base_k + q * 8]);
            }
            asm volatile("cp.async.commit_group;");
        }

        // Compute slab s after this pair's group lands; 64-thread pair barrier
#define REC_SLAB(s, wcnt)                                                          \
        {                                                                          \
            asm volatile("cp.async.wait_group %0;" :: "n"(wcnt));                  \
            BAR_SYNC(pair_bar, 64);                                                \
            const __half* hbuf = hsm + (s) * 64 * HS_STR;                          \
            const int kw = (s) * KSLAB;                                            \
            _Pragma("unroll")                                                      \
            for (int ks = 0; ks < 8; ks++) {                                       \
                const int kk0 = warp_k * 128 + ks * 16;                            \
                unsigned a0, a1, a2, a3;                                           \
                unsigned aaddr = s2u(&hbuf[(warp_m * 16 + a_row_off) * HS_STR      \
                                           + kk0 + a_k_off]);                      \
                LDSM_X4(a0, a1, a2, a3, aaddr);                                    \
                unsigned bf0, bf1, bf2, bf3;                                       \
                unsigned baddr = s2u(&ws[(kw + kk0 + bt_row) * WS_STR              \
                                         + warp_c * 16 + bt_c8]);                  \
                LDSM_X4T(bf0, bf1, bf2, bf3, baddr);                               \
                MMA16816F16(d[0][0], d[0][1], d[0][2], d[0][3],                    \
                            a0, a1, a2, a3, bf0, bf1);                             \
                MMA16816F16(d[1][0], d[1][1], d[1][2], d[1][3],                    \
                            a0, a1, a2, a3, bf2, bf3);                             \
            }                                                                      \
        }

        REC_SLAB(0, 3)
        REC_SLAB(1, 2)
        REC_SLAB(2, 1)
        REC_SLAB(3, 0)
#undef REC_SLAB

        __syncthreads();   // all pairs done computing; zbuf (stages 0-1) safe

        // Scatter partials: zbuf[warp_k][n][c]; warp tile = 16 rows x 16 cols
        {
            const int r4 = lane >> 2;
            const int c2 = (lane & 3) * 2;
            const int nb = warp_m * 16 + r4;
#pragma unroll
            for (int ct = 0; ct < 2; ct++) {
                const int c = warp_c * 16 + ct * 8 + c2;
                zbuf[(warp_k * 64 + nb) * 33 + c] = d[ct][0];
                zbuf[(warp_k * 64 + nb) * 33 + c + 1] = d[ct][1];
                zbuf[(warp_k * 64 + nb + 8) * 33 + c] = d[ct][2];
                zbuf[(warp_k * 64 + nb + 8) * 33 + c + 1] = d[ct][3];
            }
        }
        __syncthreads();

        // Gate epilogue: 1 fixed (n, j) output per thread; c in register
        {
            const int n = e_n, col = J0 + e_j;
            float zi = zbuf[n * 33 + e_j +  0] + zbuf[(64 + n) * 33 + e_j +  0] + x0;
            float zf = zbuf[n * 33 + e_j +  8] + zbuf[(64 + n) * 33 + e_j +  8] + x1;
            float zo = zbuf[n * 33 + e_j + 16] + zbuf[(64 + n) * 33 + e_j + 16] + x2;
            float zg = zbuf[n * 33 + e_j + 24] + zbuf[(64 + n) * 33 + e_j + 24] + x3;

            float iv = fsig(zi);
            float fv = fsig(zf);
            float ov = fsig(zo);
            float gv = ftanh(zg);

            float cn = fv * creg + iv * gv;
            creg = cn;
            float hn = ov * ftanh(cn);

            g_hf[par ^ 1][n * HH + col] = __float2half_rn(hn);
            out[((size_t)n * TT + t) * HH + col] = hn;
        }

        // Grid-wide barrier v2 (slot arrivals + block-0 aggregation)
        if (t + 1 < TT) {
            const unsigned target = (unsigned)(t + 1);
            __syncthreads();                    // all h writes done (CTA scope)
            if (tid == 0) st_release(&g_arrive[blk], target);
            if (blk == 0) {
                if (tid < 128) spin_until(&g_arrive[tid], target);
                __syncthreads();
                if (tid == 0) st_release(&g_phase, target);
            }
            if (tid == 0) spin_until(&g_phase, target);
            __syncthreads();
        }
    }
}

// ---------------------------------------------------------------------------
// Launcher (graph-capturable: kernel launches only)
// ---------------------------------------------------------------------------
extern "C" void kernel_launch(void* const* d_in, const int* in_sizes, int n_in,
                              void* d_out, int out_size) {
    const float* x  = (const float*)d_in[0];
    const float* h0 = (const float*)d_in[1];
    const float* Wx = (const float*)d_in[2];
    const float* Wh = (const float*)d_in[3];
    const float* b  = (const float*)d_in[4];
    float* out = (float*)d_out;

    static int attr_set = 0;
    if (!attr_set) {
        cudaFuncSetAttribute(lstm_persistent,
                             cudaFuncAttributeMaxDynamicSharedMemorySize, P_SMEM);
        cudaFuncSetAttribute(gemm1_mma,
                             cudaFuncAttributeMaxDynamicSharedMemorySize, G1_SMEM);
        attr_set = 1;
    }

    init_kernel<<<(NB * HH + 255) / 256, 256>>>(h0);
    split_wh_kernel<<<(DD * FH / 8 + 255) / 256, 256>>>(Wh);
    split_wx_kernel<<<((size_t)DD * FH / 8 + 255) / 256, 256>>>(Wx);
    split_x_kernel<<<((size_t)MM * DD / 4 + 255) / 256, 256>>>(x);

    dim3 g1(FH / 128, MM / 128);   // (32, 256)
    gemm1_mma<<<g1, 256, G1_SMEM>>>(b);

    lstm_persistent<<<128, 512, P_SMEM>>>(out);
}